// round 2
// baseline (speedup 1.0000x reference)
#include <cuda_runtime.h>
#include <math.h>

#define NN 4
#define CC 512
#define DD 768
#define HH 12
#define EE 20
#define MMENT 4
#define PP 380
#define NP 1520
#define LL 97
#define DIM2 1536
#define DIM3 2304
#define DIM4 3072
#define NEGV (-1e30f)

// ---------------- static device scratch ----------------
__device__ float g_eemb[NN*EE*MMENT*DD];
__device__ float g_eatt[NN*EE*MMENT*CC];
__device__ float g_glob[NN*EE*DD];
__device__ float g_A[NN*EE*DD];
__device__ float g_B[NN*EE*DD];
__device__ float g_edge[NN*EE*EE*DD];
__device__ float g_q[NP*DIM2];
__device__ float g_pa[NP*CC];
__device__ float g_hcat[NP*DIM3];
__device__ float g_tcat[NP*DIM3];
__device__ float g_qW[NP*DIM4];
__device__ float g_pathraw[NP*DIM4];
__device__ float g_hs[NP*DD];
__device__ float g_ts[NP*DD];
__device__ float g_part[4*NP*DD];   // 4,669,440 floats; also fits qW(S=1) & bil partials

// ---------------- K1: gather e_emb, head-mean e_att, logsumexp glob ----------------
__global__ void k_gather(const float* __restrict__ seq, const float* __restrict__ att,
                         const int* __restrict__ ms)
{
    int ne = blockIdx.x;            // n*EE + e
    int n  = ne / EE;
    int tid = threadIdx.x;
    for (int m = 0; m < MMENT; m++) {
        int pos = ms[ne*MMENT + m] + 1;
        const float* srow = seq + ((size_t)n*CC + pos)*DD;
        float* erow = g_eemb + ((size_t)ne*MMENT + m)*DD;
        for (int d = tid; d < DD; d += blockDim.x) erow[d] = srow[d];
        float* arow = g_eatt + ((size_t)ne*MMENT + m)*CC;
        for (int c = tid; c < CC; c += blockDim.x) {
            float s = 0.f;
            #pragma unroll
            for (int h = 0; h < HH; h++)
                s += att[(((size_t)n*HH + h)*CC + pos)*CC + c];
            arow[c] = s * (1.0f/HH);
        }
    }
    __syncthreads();
    for (int d = tid; d < DD; d += blockDim.x) {
        float x0 = g_eemb[((size_t)ne*MMENT+0)*DD+d];
        float x1 = g_eemb[((size_t)ne*MMENT+1)*DD+d];
        float x2 = g_eemb[((size_t)ne*MMENT+2)*DD+d];
        float x3 = g_eemb[((size_t)ne*MMENT+3)*DD+d];
        float mx = fmaxf(fmaxf(x0,x1), fmaxf(x2,x3));
        float s = expf(x0-mx)+expf(x1-mx)+expf(x2-mx)+expf(x3-mx);
        g_glob[(size_t)ne*DD + d] = mx + logf(s);
    }
}

// ---------------- K3: edge = relu(A[u] + B[v] + bm) ----------------
__global__ void k_edge(const float* __restrict__ bm)
{
    int idx = blockIdx.x*blockDim.x + threadIdx.x;
    const int total = NN*EE*EE*DD;
    if (idx >= total) return;
    int d = idx % DD;
    int v = (idx / DD) % EE;
    int u = (idx / (DD*EE)) % EE;
    int n = idx / (DD*EE*EE);
    float val = g_A[((size_t)n*EE+u)*DD+d] + g_B[((size_t)n*EE+v)*DD+d] + bm[d];
    g_edge[idx] = fmaxf(val, 0.f);
}

// ---------------- K4: pair attention, new_hs/new_ts, pa ----------------
__global__ void k_pair(const int* __restrict__ hts, const int* __restrict__ ms)
{
    int r = blockIdx.x;
    int n = r / PP;
    int h = hts[r*2 + 0];
    int t = hts[r*2 + 1];
    __shared__ int   s_ph[MMENT], s_pt[MMENT];
    __shared__ float s_phatt[MMENT], s_ptatt[MMENT];
    __shared__ float s_red[256];
    int tid = threadIdx.x;
    if (tid < MMENT) {
        s_ph[tid] = ms[((size_t)n*EE+h)*MMENT + tid] + 1;
        s_pt[tid] = ms[((size_t)n*EE+t)*MMENT + tid] + 1;
    }
    __syncthreads();
    if (tid < 2*MMENT) {
        int m2 = tid & (MMENT-1);
        float s = 0.f;
        if (tid < MMENT) {
            for (int m1 = 0; m1 < MMENT; m1++)
                s += g_eatt[((size_t)(n*EE+h)*MMENT+m1)*CC + s_pt[m2]];
            s_phatt[m2] = s * (1.f/MMENT);
        } else {
            for (int m1 = 0; m1 < MMENT; m1++)
                s += g_eatt[((size_t)(n*EE+t)*MMENT+m1)*CC + s_ph[m2]];
            s_ptatt[m2] = s * (1.f/MMENT);
        }
    }
    __syncthreads();
    if (tid == 0) {
        float sh = 1e-5f, st = 1e-5f;
        for (int m = 0; m < MMENT; m++) { sh += s_phatt[m]; st += s_ptatt[m]; }
        float ih = 1.f/sh, it = 1.f/st;
        for (int m = 0; m < MMENT; m++) { s_phatt[m] *= ih; s_ptatt[m] *= it; }
    }
    __syncthreads();
    for (int d = tid; d < DD; d += blockDim.x) {
        float nh = 0.f, nt = 0.f;
        #pragma unroll
        for (int m = 0; m < MMENT; m++) {
            nh += s_ptatt[m]*g_eemb[((size_t)(n*EE+h)*MMENT+m)*DD + d];
            nt += s_phatt[m]*g_eemb[((size_t)(n*EE+t)*MMENT+m)*DD + d];
        }
        g_hcat[(size_t)r*DIM3 + d] = nh;
        g_tcat[(size_t)r*DIM3 + d] = nt;
        g_q[(size_t)r*DIM2 + d]       = nh;
        g_q[(size_t)r*DIM2 + DD + d]  = nt;
    }
    float local = 0.f;
    for (int c = tid; c < CC; c += blockDim.x) {
        float na = 0.f, ta = 0.f;
        #pragma unroll
        for (int m = 0; m < MMENT; m++) {
            na += s_ptatt[m]*g_eatt[((size_t)(n*EE+h)*MMENT+m)*CC + c];
            ta += s_phatt[m]*g_eatt[((size_t)(n*EE+t)*MMENT+m)*CC + c];
        }
        float v = na*ta;
        g_pa[(size_t)r*CC + c] = v;
        local += v;
    }
    s_red[tid] = local;
    __syncthreads();
    for (int off = 128; off > 0; off >>= 1) {
        if (tid < off) s_red[tid] += s_red[tid+off];
        __syncthreads();
    }
    float inv = 1.f/(s_red[0] + 1e-5f);
    for (int c = tid; c < CC; c += blockDim.x)
        g_pa[(size_t)r*CC + c] *= inv;
}

// ---------------- generic SGEMM 128x128x8, batched + split-K → partials ----------------
__global__ void __launch_bounds__(256) sgemm(
    int M, int Nn, int Kc, int S,
    const float* __restrict__ A, int lda, long long sA,
    const float* __restrict__ B, int ldb, long long sB,
    float* __restrict__ part, int Mtot)
{
    int b = blockIdx.z / S;
    int s = blockIdx.z % S;
    const float* Ab = A + (size_t)b*sA + (size_t)s*Kc;
    const float* Bb = B + (size_t)b*sB + (size_t)s*Kc*ldb;
    int m0 = blockIdx.y*128, n0 = blockIdx.x*128;
    __shared__ float As[8][128];
    __shared__ float Bs[8][128];
    int tid = threadIdx.x;
    int arow = tid >> 1, ak = (tid & 1)*4;
    int bk = tid >> 5,  bn = (tid & 31)*4;
    int tx = tid & 15,  ty = tid >> 4;
    float acc[8][8];
    #pragma unroll
    for (int i = 0; i < 8; i++)
        #pragma unroll
        for (int j = 0; j < 8; j++) acc[i][j] = 0.f;
    for (int k0 = 0; k0 < Kc; k0 += 8) {
        float4 av = make_float4(0.f,0.f,0.f,0.f);
        if (m0 + arow < M)
            av = *(const float4*)(Ab + (size_t)(m0+arow)*lda + k0 + ak);
        float4 bv = *(const float4*)(Bb + (size_t)(k0+bk)*ldb + n0 + bn);
        __syncthreads();
        As[ak+0][arow] = av.x; As[ak+1][arow] = av.y;
        As[ak+2][arow] = av.z; As[ak+3][arow] = av.w;
        *(float4*)&Bs[bk][bn] = bv;
        __syncthreads();
        #pragma unroll
        for (int kk = 0; kk < 8; kk++) {
            float a[8], bb[8];
            *(float4*)(a)    = *(const float4*)&As[kk][ty*8];
            *(float4*)(a+4)  = *(const float4*)&As[kk][ty*8+4];
            *(float4*)(bb)   = *(const float4*)&Bs[kk][tx*8];
            *(float4*)(bb+4) = *(const float4*)&Bs[kk][tx*8+4];
            #pragma unroll
            for (int i = 0; i < 8; i++)
                #pragma unroll
                for (int j = 0; j < 8; j++)
                    acc[i][j] += a[i]*bb[j];
        }
    }
    float* pbase = part + ((size_t)s*Mtot + (size_t)b*M)*Nn;
    #pragma unroll
    for (int i = 0; i < 8; i++) {
        int r = m0 + ty*8 + i;
        if (r < M) {
            float* prow = pbase + (size_t)r*Nn + n0 + tx*8;
            *(float4*)(prow)   = make_float4(acc[i][0],acc[i][1],acc[i][2],acc[i][3]);
            *(float4*)(prow+4) = make_float4(acc[i][4],acc[i][5],acc[i][6],acc[i][7]);
        }
    }
}

// ---------------- reduce partials + bias + relu + dual store ----------------
__global__ void reduce_ep(const float* __restrict__ part, int S, int Mtot, int Nn,
                          const float* __restrict__ bias, int dorelu,
                          float* __restrict__ dst1, int ld1,
                          float* __restrict__ dst2, int ld2)
{
    int idx = blockIdx.x*blockDim.x + threadIdx.x;
    if (idx >= Mtot*Nn) return;
    int r = idx / Nn, c = idx % Nn;
    float v = 0.f;
    for (int s = 0; s < S; s++)
        v += part[((size_t)s*Mtot + r)*Nn + c];
    if (bias) v += bias[c];
    if (dorelu) v = fmaxf(v, 0.f);
    dst1[(size_t)r*ld1 + c] = v;
    if (dst2) dst2[(size_t)r*ld2 + c] = v;
}

// ---------------- K7: score + masked softmax + path features ----------------
__global__ void k_scorepath(const int* __restrict__ hts, const float* __restrict__ battp)
{
    int r = blockIdx.x;
    int n = r / PP;
    int h = hts[r*2 + 0];
    int t = hts[r*2 + 1];
    __shared__ float s_q[DIM4];
    __shared__ float s_score[EE];
    __shared__ float s_aw[EE];
    int tid = threadIdx.x;
    for (int i = tid; i < DIM4; i += blockDim.x)
        s_q[i] = g_qW[(size_t)r*DIM4 + i];
    __syncthreads();
    int warp = tid >> 5, lane = tid & 31;
    float batt = battp[0];
    for (int v = warp; v < EE; v += 8) {
        const float* e1 = g_edge + ((size_t)((n*EE+h)*EE + v))*DD;
        const float* e2 = g_edge + ((size_t)((n*EE+v)*EE + t))*DD;
        const float* e3 = g_edge + ((size_t)((n*EE+t)*EE + v))*DD;
        const float* e4 = g_edge + ((size_t)((n*EE+v)*EE + h))*DD;
        float s = 0.f;
        for (int d = lane; d < DD; d += 32)
            s += s_q[d]*e1[d] + s_q[DD+d]*e2[d] + s_q[2*DD+d]*e3[d] + s_q[3*DD+d]*e4[d];
        #pragma unroll
        for (int off = 16; off; off >>= 1)
            s += __shfl_down_sync(0xffffffffu, s, off);
        if (lane == 0) s_score[v] = s + batt;
    }
    __syncthreads();
    if (tid == 0) {
        float mx = -1e38f;
        for (int v = 0; v < EE; v++) {
            float sc = (v == h || v == t) ? NEGV : s_score[v];
            s_score[v] = sc;
            mx = fmaxf(mx, sc);
        }
        float sum = 0.f;
        for (int v = 0; v < EE; v++) {
            float e = expf(s_score[v] - mx);
            s_aw[v] = e;
            sum += e;
        }
        float inv = 1.f/sum;
        for (int v = 0; v < EE; v++) s_aw[v] *= inv;
    }
    __syncthreads();
    for (int idx = tid; idx < DIM4; idx += blockDim.x) {
        int kk = idx / DD, d = idx % DD;
        const float* ep;
        size_t strideV;
        if (kk == 0)      { ep = g_edge + ((size_t)((n*EE+h)*EE))*DD + d;   strideV = DD; }
        else if (kk == 1) { ep = g_edge + ((size_t)(n*EE)*EE + t)*DD + d;   strideV = (size_t)EE*DD; }
        else if (kk == 2) { ep = g_edge + ((size_t)((n*EE+t)*EE))*DD + d;   strideV = DD; }
        else              { ep = g_edge + ((size_t)(n*EE)*EE + h)*DD + d;   strideV = (size_t)EE*DD; }
        float acc = 0.f;
        #pragma unroll 4
        for (int v = 0; v < EE; v++)
            acc += s_aw[v]*ep[(size_t)v*strideV];
        g_pathraw[(size_t)r*DIM4 + idx] = acc;
    }
}

// ---------------- K10: bilinear GEMM, on-the-fly hs⊗ts A operand ----------------
__global__ void __launch_bounds__(256) k_bil(const float* __restrict__ Wbil)
{
    __shared__ float ts_s[64][68];
    __shared__ float Ws[64*97];
    int r0 = blockIdx.x * 64;
    int k  = blockIdx.y;            // 0..11
    int tid = threadIdx.x;
    for (int idx = tid; idx < 64*64; idx += 256) {
        int rr = idx >> 6, j = idx & 63;
        int r = r0 + rr;
        ts_s[j][rr] = (r < NP) ? g_ts[(size_t)r*DD + k*64 + j] : 0.f;
    }
    int tx = tid & 15, ty = tid >> 4;
    int cols[7];
    #pragma unroll
    for (int ci = 0; ci < 7; ci++) {
        int c = ty + 16*ci;
        cols[ci] = (c < LL) ? c : 0;
    }
    float acc[4][7];
    #pragma unroll
    for (int ri = 0; ri < 4; ri++)
        #pragma unroll
        for (int ci = 0; ci < 7; ci++) acc[ri][ci] = 0.f;
    for (int i = 0; i < 64; i++) {
        __syncthreads();
        for (int idx = tid; idx < 64*97; idx += 256)
            Ws[idx] = Wbil[(size_t)(k*4096 + i*64)*LL + idx];
        __syncthreads();
        float acc2[4][7];
        #pragma unroll
        for (int ri = 0; ri < 4; ri++)
            #pragma unroll
            for (int ci = 0; ci < 7; ci++) acc2[ri][ci] = 0.f;
        #pragma unroll 4
        for (int j = 0; j < 64; j++) {
            float4 tv4 = *(const float4*)&ts_s[j][tx*4];
            float tvv[4] = {tv4.x, tv4.y, tv4.z, tv4.w};
            #pragma unroll
            for (int ci = 0; ci < 7; ci++) {
                float w = Ws[j*LL + cols[ci]];
                #pragma unroll
                for (int ri = 0; ri < 4; ri++)
                    acc2[ri][ci] += tvv[ri]*w;
            }
        }
        #pragma unroll
        for (int ri = 0; ri < 4; ri++) {
            int r = r0 + tx*4 + ri;
            float hv = (r < NP) ? g_hs[(size_t)r*DD + k*64 + i] : 0.f;
            #pragma unroll
            for (int ci = 0; ci < 7; ci++)
                acc[ri][ci] += hv*acc2[ri][ci];
        }
    }
    #pragma unroll
    for (int ri = 0; ri < 4; ri++) {
        int r = r0 + tx*4 + ri;
        if (r < NP) {
            #pragma unroll
            for (int ci = 0; ci < 7; ci++) {
                int c = ty + 16*ci;
                if (c < LL)
                    g_part[((size_t)k*NP + r)*LL + c] = acc[ri][ci];
            }
        }
    }
}

__global__ void k_bilred(const float* __restrict__ bbil, float* __restrict__ out)
{
    int idx = blockIdx.x*blockDim.x + threadIdx.x;
    if (idx >= NP*LL) return;
    int r = idx / LL, l = idx % LL;
    float v = bbil[l];
    #pragma unroll
    for (int k = 0; k < 12; k++)
        v += g_part[((size_t)k*NP + r)*LL + l];
    out[idx] = v;
}

// ---------------- launcher ----------------
static float* symaddr(const void* sym)
{
    void* p = nullptr;
    cudaGetSymbolAddress(&p, sym);
    return (float*)p;
}

extern "C" void kernel_launch(void* const* d_in, const int* in_sizes, int n_in,
                              void* d_out, int out_size)
{
    const float* seq   = (const float*)d_in[0];
    const float* att   = (const float*)d_in[1];
    const int*   ms    = (const int*)  d_in[2];
    const int*   hts   = (const int*)  d_in[3];
    const float* Wm1   = (const float*)d_in[4];
    const float* Wm2   = (const float*)d_in[5];
    const float* bm    = (const float*)d_in[6];
    const float* Watt  = (const float*)d_in[7];
    const float* batt  = (const float*)d_in[8];
    const float* Wpath = (const float*)d_in[9];
    const float* bpath = (const float*)d_in[10];
    const float* Whead = (const float*)d_in[11];
    const float* bhead = (const float*)d_in[12];
    const float* Wtail = (const float*)d_in[13];
    const float* btail = (const float*)d_in[14];
    const float* Wbil  = (const float*)d_in[15];
    const float* bbil  = (const float*)d_in[16];
    float* out = (float*)d_out;

    float* glob   = symaddr(g_glob);
    float* gA     = symaddr(g_A);
    float* gB     = symaddr(g_B);
    float* q      = symaddr(g_q);
    float* pa     = symaddr(g_pa);
    float* hcat   = symaddr(g_hcat);
    float* tcat   = symaddr(g_tcat);
    float* qW     = symaddr(g_qW);
    float* praw   = symaddr(g_pathraw);
    float* hs     = symaddr(g_hs);
    float* ts     = symaddr(g_ts);
    float* part   = symaddr(g_part);

    // 1. gather
    k_gather<<<NN*EE, 256>>>(seq, att, ms);

    // 2. A = glob @ Wm1 ; B = glob @ Wm2   (M=80, N=768, K=768)
    sgemm<<<dim3(6,1,1), 256>>>(NN*EE, DD, DD, 1, glob, DD, 0, Wm1, DD, 0, part, NN*EE);
    reduce_ep<<<(NN*EE*DD+255)/256, 256>>>(part, 1, NN*EE, DD, nullptr, 0, gA, DD, nullptr, 0);
    sgemm<<<dim3(6,1,1), 256>>>(NN*EE, DD, DD, 1, glob, DD, 0, Wm2, DD, 0, part, NN*EE);
    reduce_ep<<<(NN*EE*DD+255)/256, 256>>>(part, 1, NN*EE, DD, nullptr, 0, gB, DD, nullptr, 0);

    // 3. edge
    k_edge<<<(NN*EE*EE*DD+255)/256, 256>>>(bm);

    // 4. pair attention -> q, hcat[:, :D], tcat[:, :D], pa
    k_pair<<<NP, 256>>>(hts, ms);

    // 5. rs = pa @ seq (batched per doc), write into hcat/tcat cols [D, 2D)
    sgemm<<<dim3(6,3,NN*2), 256>>>(PP, DD, CC/2, 2, pa, CC, (long long)PP*CC,
                                   seq, DD, (long long)CC*DD, part, NP);
    reduce_ep<<<(NP*DD+255)/256, 256>>>(part, 2, NP, DD, nullptr, 0,
                                        hcat + DD, DIM3, tcat + DD, DIM3);

    // 6. qW = q @ Watt  (1520 x 3072, K=1536)
    sgemm<<<dim3(24,12,1), 256>>>(NP, DIM4, DIM2, 1, q, DIM2, 0, Watt, DIM4, 0, part, NP);
    reduce_ep<<<(NP*DIM4+255)/256, 256>>>(part, 1, NP, DIM4, nullptr, 0, qW, DIM4, nullptr, 0);

    // 7. score/softmax/path features
    k_scorepath<<<NP, 256>>>(hts, batt);

    // 8. path = relu(pathraw @ Wpath + bpath) -> hcat/tcat cols [2D, 3D)
    sgemm<<<dim3(6,12,4), 256>>>(NP, DD, DIM4/4, 4, praw, DIM4, 0, Wpath, DD, 0, part, NP);
    reduce_ep<<<(NP*DD+255)/256, 256>>>(part, 4, NP, DD, bpath, 1,
                                        hcat + 2*DD, DIM3, tcat + 2*DD, DIM3);

    // 9. hs = relu(hcat @ Whead + bhead) ; ts = relu(tcat @ Wtail + btail)
    sgemm<<<dim3(6,12,4), 256>>>(NP, DD, DIM3/4, 4, hcat, DIM3, 0, Whead, DD, 0, part, NP);
    reduce_ep<<<(NP*DD+255)/256, 256>>>(part, 4, NP, DD, bhead, 1, hs, DD, nullptr, 0);
    sgemm<<<dim3(6,12,4), 256>>>(NP, DD, DIM3/4, 4, tcat, DIM3, 0, Wtail, DD, 0, part, NP);
    reduce_ep<<<(NP*DD+255)/256, 256>>>(part, 4, NP, DD, btail, 1, ts, DD, nullptr, 0);

    // 10. bilinear head
    k_bil<<<dim3((NP+63)/64, 12), 256>>>(Wbil);
    k_bilred<<<(NP*LL+255)/256, 256>>>(bbil, out);
}